// round 7
// baseline (speedup 1.0000x reference)
#include <cuda_runtime.h>
#include <cuda_bf16.h>

// Problem constants: T=1024, C_in=4, C_out=2, H=32
#define T_LEN 1024
#define H_DIM 32
#define NP    132          // 128 (h,c) pairs + 4 plain-x pairs (for b2 term)
#define PITCH 160          // padded pair-pitch: 640B rows, 128B-aligned

// Scan storage, [i][p] layout (coalesced for the combine kernel).
__device__ float g_S[T_LEN][PITCH];     // 640 KB
__device__ float g_C[T_LEN][PITCH];     // 640 KB
// Hierarchical scan offsets: [quarter Q][warp qw][pair], and quarter totals.
__device__ float g_offS[4][4][PITCH];
__device__ float g_offC[4][4][PITCH];
__device__ float g_qtS[4][PITCH];
__device__ float g_qtC[4][PITCH];

// ---------------------------------------------------------------------------
// Kernel 1: scans. CTA (p, Q) = (bid>>2, bid&3) scans j in [Q*256, Q*256+256)
// of pair p. Warp qw scans its 64-chunk (2 shuffle-scan blocks with carry),
// stores LOCAL inclusive scans; thread 0 stores within-CTA exclusive warp
// offsets and the quarter total. Pair p<128: (h=p>>2, c=p&3), value =
// sincos(w1[h,0]*t_j)*x[j,c]. Pair p>=128: a=0 -> C scan = plain x prefix.
// ---------------------------------------------------------------------------
__global__ void __launch_bounds__(128)
ck_scan_kernel(const float* __restrict__ x,   // [T,4]
               const float* __restrict__ t,   // [T]
               const float* __restrict__ w1)  // [H,3]
{
    const int bid  = blockIdx.x;
    const int p    = bid >> 2;
    const int Q    = bid & 3;
    const int tid  = threadIdx.x;
    const int warp = tid >> 5;
    const int lane = tid & 31;

    const int c = (p < 128) ? (p & 3) : (p - 128);
    const float a = (p < 128) ? __ldg(&w1[3 * (p >> 2)]) : 0.0f;

    const int j0 = Q * 256 + warp * 64;
    float carS = 0.0f, carC = 0.0f;

#pragma unroll
    for (int blk = 0; blk < 2; ++blk) {
        int j = j0 + blk * 32 + lane;
        float tj = __ldg(&t[j]);
        float xv = __ldg(&x[j * 4 + c]);
        float sj, cj;
        __sincosf(a * tj, &sj, &cj);
        float vS = sj * xv;
        float vC = cj * xv;
        // Inclusive warp scans (two interleaved chains).
#pragma unroll
        for (int o2 = 1; o2 < 32; o2 <<= 1) {
            float nS = __shfl_up_sync(0xffffffffu, vS, o2);
            float nC = __shfl_up_sync(0xffffffffu, vC, o2);
            if (lane >= o2) { vS += nS; vC += nC; }
        }
        vS += carS; vC += carC;
        g_S[j][p] = vS;
        g_C[j][p] = vC;
        carS = __shfl_sync(0xffffffffu, vS, 31);
        carC = __shfl_sync(0xffffffffu, vC, 31);
    }

    __shared__ float tS[4], tC[4];
    if (lane == 0) { tS[warp] = carS; tC[warp] = carC; }
    __syncthreads();

    if (tid == 0) {
        float eS = 0.0f, eC = 0.0f;
#pragma unroll
        for (int qw = 0; qw < 4; ++qw) {
            g_offS[Q][qw][p] = eS;
            g_offC[Q][qw][p] = eC;
            eS += tS[qw];
            eC += tC[qw];
        }
        g_qtS[Q][p] = eS;   // quarter total
        g_qtC[Q][p] = eC;
    }
}

// ---------------------------------------------------------------------------
// Kernel 2: combine. CTA = output row i; thread l = pair p=l (threads 0..3
// also fold in the plain-x pair 128+l, giving the b2*X[i] term).
// y[i,o] = sum_p A_op*(ci*S - si*C) + B_op*(ci*C + si*S) + b2*X[i],
// A = w2*cos(phase), B = w2*sin(phase), phase = c*w1[h,1] + o*w1[h,2] + b1[h].
// All loads coalesced ([i][p] layout). Fixed reduction tree -> deterministic.
// ---------------------------------------------------------------------------
__global__ void __launch_bounds__(128)
ck_combine_kernel(const float* __restrict__ t,   // [T]
                  const float* __restrict__ w1,  // [H,3]
                  const float* __restrict__ b1,  // [H]
                  const float* __restrict__ w2,  // [H]
                  const float* __restrict__ b2,  // [1]
                  float* __restrict__ y)         // [T,2]
{
    const int i    = blockIdx.x;
    const int l    = threadIdx.x;       // pair index
    const int warp = l >> 5;
    const int lane = l & 31;
    const int Q    = i >> 8;
    const int qw   = (i >> 6) & 3;

    // Global prefix for pair l at position i.
    float S = g_S[i][l] + g_offS[Q][qw][l];
    float C = g_C[i][l] + g_offC[Q][qw][l];
    if (Q > 0) { S += g_qtS[0][l]; C += g_qtC[0][l]; }
    if (Q > 1) { S += g_qtS[1][l]; C += g_qtC[1][l]; }
    if (Q > 2) { S += g_qtS[2][l]; C += g_qtC[2][l]; }

    const int h = l >> 2;
    const int c = l & 3;
    const float ti  = __ldg(&t[i]);
    const float a   = __ldg(&w1[3 * h]);
    const float w11 = __ldg(&w1[3 * h + 1]);
    const float w12 = __ldg(&w1[3 * h + 2]);
    const float bb  = __ldg(&b1[h]);
    const float w   = __ldg(&w2[h]);

    float si, ci;
    __sincosf(a * ti, &si, &ci);
    float u = ci * S - si * C;          // windowed sin-sum
    float v = ci * C + si * S;          // windowed cos-sum

    float ph = fmaf((float)c, w11, bb);
    float s0, c0, s1, c1;
    __sincosf(ph, &s0, &c0);
    __sincosf(ph + w12, &s1, &c1);
    float y0 = w * fmaf(c0, u, s0 * v);
    float y1 = w * fmaf(c1, u, s1 * v);

    // Plain-x pairs (128..131): contribution b2 * X_c[i] to both outputs.
    if (l < 4) {
        int pe = 128 + l;
        float Ce = g_C[i][pe] + g_offC[Q][qw][pe];
        if (Q > 0) Ce += g_qtC[0][pe];
        if (Q > 1) Ce += g_qtC[1][pe];
        if (Q > 2) Ce += g_qtC[2][pe];
        float e = __ldg(&b2[0]) * Ce;
        y0 += e;
        y1 += e;
    }

    // Reduce 128 threads -> 2 outputs (fixed tree).
#pragma unroll
    for (int off = 16; off > 0; off >>= 1) {
        y0 += __shfl_xor_sync(0xffffffffu, y0, off);
        y1 += __shfl_xor_sync(0xffffffffu, y1, off);
    }
    __shared__ float2 part[4];
    if (lane == 0) part[warp] = make_float2(y0, y1);
    __syncthreads();
    if (l == 0) {
        float2 p0 = part[0], p1 = part[1], p2 = part[2], p3 = part[3];
        ((float2*)y)[i] = make_float2((p0.x + p1.x) + (p2.x + p3.x),
                                      (p0.y + p1.y) + (p2.y + p3.y));
    }
}

// ---------------------------------------------------------------------------
// Inputs (metadata order): x[T*4], t[T], w1[H*3], b1[H], w2[H], b2[1],
// out_channels (unused — compile-time constant).
// ---------------------------------------------------------------------------
extern "C" void kernel_launch(void* const* d_in, const int* in_sizes, int n_in,
                              void* d_out, int out_size)
{
    const float* x  = (const float*)d_in[0];
    const float* t  = (const float*)d_in[1];
    const float* w1 = (const float*)d_in[2];
    const float* b1 = (const float*)d_in[3];
    const float* w2 = (const float*)d_in[4];
    const float* b2 = (const float*)d_in[5];
    float* y = (float*)d_out;

    ck_scan_kernel<<<NP * 4, 128>>>(x, t, w1);
    ck_combine_kernel<<<T_LEN, 128>>>(t, w1, b1, w2, b2, y);
}